// round 9
// baseline (speedup 1.0000x reference)
#include <cuda_runtime.h>

#define BT   65536       // batch
#define KM   31          // DIM-1 stacked MLPs
#define BLK  128         // threads per main block; 2 rows/thread -> 256 rows/block

typedef unsigned long long ull;

// ---------------- scratch (device globals: allocation-free) ----------------
__device__ float g_xt[32 * BT];   // x transposed: g_xt[j*BT + b]
__device__ float g_s [KM * BT];   // per-k scale logits: g_s[k*BT + b]

// ---------------- f32x2 helpers ----------------
__device__ __forceinline__ ull ffma2(ull a, ull b, ull c) {
    ull d; asm("fma.rn.f32x2 %0, %1, %2, %3;" : "=l"(d) : "l"(a), "l"(b), "l"(c)); return d;
}
__device__ __forceinline__ ull dup2(float a) {
    ull d; asm("mov.b64 %0, {%1, %1};" : "=l"(d) : "f"(a)); return d;
}
__device__ __forceinline__ void unpack2(ull v, float& lo, float& hi) {
    asm("mov.b64 {%0, %1}, %2;" : "=f"(lo), "=f"(hi) : "l"(v));
}
__device__ __forceinline__ float lrelu(float v) { return fmaxf(v, 0.2f * v); }

// ---------------- smem layout (float offsets), all 16B aligned ----------------
#define XS   0            // x slice [j][r]: up to 32*256
#define W1T  8192         // W1 transposed [j=32][h=24]
#define B1   8960         // 24
#define W2T  8984         // W2 transposed [h=24][H=24]
#define B2   9560
#define W3T  9584
#define B3   10160
#define W4T  10184        // W4 transposed [h=24][o=2]  (s,t) pairs
#define B4   10232        // 2
#define SMF  10236

// 24->24 layer on a row-pair: inputs a0/a1 (24 scalars each, registers),
// weights transposed in smem (pairs (H,H+1) contiguous), outputs o0/o1.
__device__ __forceinline__ void layer24(const float* __restrict__ a0,
                                        const float* __restrict__ a1,
                                        const float* wt, const float* bias,
                                        float* __restrict__ o0,
                                        float* __restrict__ o1)
{
    ull acc0[12], acc1[12];
    const ull* bp = (const ull*)bias;
    #pragma unroll
    for (int p = 0; p < 12; ++p) { acc0[p] = bp[p]; acc1[p] = bp[p]; }
    #pragma unroll
    for (int h = 0; h < 24; ++h) {
        const ull pa = dup2(a0[h]);
        const ull pb = dup2(a1[h]);
        const ulonglong2* w = (const ulonglong2*)(wt + h * 24);
        #pragma unroll
        for (int q = 0; q < 6; ++q) {
            const ulonglong2 wq = w[q];
            acc0[2*q]   = ffma2(wq.x, pa, acc0[2*q]);
            acc1[2*q]   = ffma2(wq.x, pb, acc1[2*q]);
            acc0[2*q+1] = ffma2(wq.y, pa, acc0[2*q+1]);
            acc1[2*q+1] = ffma2(wq.y, pb, acc1[2*q+1]);
        }
    }
    #pragma unroll
    for (int p = 0; p < 12; ++p) {
        float lo, hi;
        unpack2(acc0[p], lo, hi); o0[2*p] = lrelu(lo); o0[2*p+1] = lrelu(hi);
        unpack2(acc1[p], lo, hi); o1[2*p] = lrelu(lo); o1[2*p+1] = lrelu(hi);
    }
}

// ---------------- kernel 1: transpose x into g_xt + dim-0 leaf output ----------------
// 512 blocks x 128 rows: high block-level parallelism; float4 global reads,
// conflict-free stride-33 smem transpose, coalesced 128B writes to g_xt.
__global__ void pack_x_kernel(const float* __restrict__ x,
                              const float* __restrict__ p0,
                              float* __restrict__ out)
{
    __shared__ float tile[128 * 33];
    const int tid  = threadIdx.x;
    const int base = blockIdx.x * 128;

    // phase 1: 4 independent LDG.128 per thread
    #pragma unroll
    for (int i = 0; i < 4; ++i) {
        const int idx = tid + i * 256;              // over 1024 float4 chunks
        const int r  = idx >> 3;
        const int jc = idx & 7;
        const float4 v = ((const float4*)x)[(size_t)(base + r) * 8 + jc];
        tile[r * 33 + 4*jc + 0] = v.x;
        tile[r * 33 + 4*jc + 1] = v.y;
        tile[r * 33 + 4*jc + 2] = v.z;
        tile[r * 33 + 4*jc + 3] = v.w;
    }
    __syncthreads();

    // phase 2: 16 independent LDS + coalesced STG.32 per thread
    #pragma unroll
    for (int i = 0; i < 16; ++i) {
        const int idx = tid + i * 256;              // over 4096 floats
        const int j = idx >> 7;
        const int r = idx & 127;
        g_xt[j * BT + base + r] = tile[r * 33 + j];
    }

    // z col 31 = x[:,0]*exp(s0)+t0  (dim-0 LeafParam)
    if (tid < 128)
        out[(size_t)(base + tid) * 32 + 31] = tile[tid * 33] * expf(p0[0]) + p0[1];
}

// ---------------- kernel 2: main — one (k, row-tile) per block ----------------
__global__ __launch_bounds__(BLK, 4)
void maf_main(const float* __restrict__ W1, const float* __restrict__ b1,
              const float* __restrict__ W2, const float* __restrict__ b2,
              const float* __restrict__ W3, const float* __restrict__ b3,
              const float* __restrict__ W4, const float* __restrict__ b4,
              float* __restrict__ out)
{
    __shared__ __align__(16) float sm[SMF];

    const int tid  = threadIdx.x;
    const int k    = blockIdx.y;
    const int base = blockIdx.x * 256;

    // ---- stage x slice (cols 0..k+1) and transposed weights ----
    {
        const int nx = (k + 2) * 256;
        for (int idx = tid; idx < nx; idx += BLK)
            sm[XS + idx] = g_xt[(idx >> 8) * BT + base + (idx & 255)];

        const float* gW1 = W1 + k * 768;
        for (int i = tid; i < 768; i += BLK) {
            const int h = i >> 5, j = i & 31;
            sm[W1T + j * 24 + h] = gW1[i];
        }
        const float* gW2 = W2 + k * 576;
        for (int i = tid; i < 576; i += BLK)
            sm[W2T + (i % 24) * 24 + (i / 24)] = gW2[i];
        const float* gW3 = W3 + k * 576;
        for (int i = tid; i < 576; i += BLK)
            sm[W3T + (i % 24) * 24 + (i / 24)] = gW3[i];
        const float* gW4 = W4 + k * 48;
        for (int i = tid; i < 48; i += BLK)
            sm[W4T + (i % 24) * 2 + (i / 24)] = gW4[i];
        if (tid < 24) {
            sm[B1 + tid] = b1[k * 24 + tid];
            sm[B2 + tid] = b2[k * 24 + tid];
            sm[B3 + tid] = b3[k * 24 + tid];
        }
        if (tid < 2) sm[B4 + tid] = b4[k * 2 + tid];
    }
    __syncthreads();

    // this thread's two rows: base+tid and base+tid+128
    float a0[24], a1[24], c0[24], c1[24];

    // ---- layer 1: (k+1) -> 24, inputs from smem x slice ----
    {
        ull acc0[12], acc1[12];
        const ull* bp = (const ull*)(sm + B1);
        #pragma unroll
        for (int p = 0; p < 12; ++p) { acc0[p] = bp[p]; acc1[p] = bp[p]; }
        for (int j = 0; j <= k; ++j) {
            const ull pa = dup2(sm[XS + j * 256 + tid]);
            const ull pb = dup2(sm[XS + j * 256 + tid + 128]);
            const ulonglong2* w = (const ulonglong2*)(sm + W1T + j * 24);
            #pragma unroll
            for (int q = 0; q < 6; ++q) {
                const ulonglong2 wq = w[q];
                acc0[2*q]   = ffma2(wq.x, pa, acc0[2*q]);
                acc1[2*q]   = ffma2(wq.x, pb, acc1[2*q]);
                acc0[2*q+1] = ffma2(wq.y, pa, acc0[2*q+1]);
                acc1[2*q+1] = ffma2(wq.y, pb, acc1[2*q+1]);
            }
        }
        #pragma unroll
        for (int p = 0; p < 12; ++p) {
            float lo, hi;
            unpack2(acc0[p], lo, hi); a0[2*p] = lrelu(lo); a0[2*p+1] = lrelu(hi);
            unpack2(acc1[p], lo, hi); a1[2*p] = lrelu(lo); a1[2*p+1] = lrelu(hi);
        }
    }

    // ---- layers 2 & 3 ----
    layer24(a0, a1, sm + W2T, sm + B2, c0, c1);
    layer24(c0, c1, sm + W3T, sm + B3, a0, a1);

    // ---- layer 4: 24 -> (s, t), natural (s,t) pairs ----
    ull st0 = *(const ull*)(sm + B4);
    ull st1 = st0;
    #pragma unroll
    for (int h = 0; h < 24; ++h) {
        const ull w  = ((const ull*)(sm + W4T))[h];
        st0 = ffma2(w, dup2(a0[h]), st0);
        st1 = ffma2(w, dup2(a1[h]), st1);
    }
    float s0, t0, s1, t1;
    unpack2(st0, s0, t0);
    unpack2(st1, s1, t1);

    // ---- outputs: z[:, 30-k] = x[:, k+1]*exp(s)+t ; s -> scratch ----
    const int r0 = base + tid;
    const int r1 = base + tid + 128;
    const float xk0 = sm[XS + (k + 1) * 256 + tid];
    const float xk1 = sm[XS + (k + 1) * 256 + tid + 128];
    out[(size_t)r0 * 32 + (30 - k)] = xk0 * expf(s0) + t0;
    out[(size_t)r1 * 32 + (30 - k)] = xk1 * expf(s1) + t1;
    g_s[k * BT + r0] = s0;
    g_s[k * BT + r1] = s1;
}

// ---------------- kernel 3: log_det reduce (float2, MLP=31) ----------------
__global__ void reduce_kernel(const float* __restrict__ p0, float* __restrict__ out)
{
    const int t = blockIdx.x * 128 + threadIdx.x;   // 32768 threads, 2 rows each
    const float s0 = p0[0];
    float2 sum = make_float2(s0, s0);
    #pragma unroll
    for (int k = 0; k < KM; ++k) {
        const float2 v = ((const float2*)(g_s + k * BT))[t];
        sum.x += v.x; sum.y += v.y;
    }
    ((float2*)(out + (size_t)BT * 32))[t] = sum;    // log_det
}

extern "C" void kernel_launch(void* const* d_in, const int* in_sizes, int n_in,
                              void* d_out, int out_size)
{
    const float* x  = (const float*)d_in[0];
    const float* p0 = (const float*)d_in[1];
    const float* W1 = (const float*)d_in[2];
    const float* b1 = (const float*)d_in[3];
    const float* W2 = (const float*)d_in[4];
    const float* b2 = (const float*)d_in[5];
    const float* W3 = (const float*)d_in[6];
    const float* b3 = (const float*)d_in[7];
    const float* W4 = (const float*)d_in[8];
    const float* b4 = (const float*)d_in[9];
    float* out = (float*)d_out;

    pack_x_kernel<<<BT / 128, 256>>>(x, p0, out);
    maf_main<<<dim3(BT / 256, KM), BLK>>>(W1, b1, W2, b2, W3, b3, W4, b4, out);
    reduce_kernel<<<BT / 256, 128>>>(p0, out);
}

// round 10
// speedup vs baseline: 1.0884x; 1.0884x over previous
#include <cuda_runtime.h>

#define BT   65536       // batch
#define KM   31          // DIM-1 stacked MLPs
#define BLK  128         // threads per main block; 2 rows/thread -> 256 rows/block

typedef unsigned long long ull;

// ---------------- scratch (device global: allocation-free) ----------------
__device__ float g_xt[32 * BT];   // x transposed: g_xt[j*BT + b]

// ---------------- f32x2 helpers ----------------
__device__ __forceinline__ ull ffma2(ull a, ull b, ull c) {
    ull d; asm("fma.rn.f32x2 %0, %1, %2, %3;" : "=l"(d) : "l"(a), "l"(b), "l"(c)); return d;
}
__device__ __forceinline__ ull dup2(float a) {
    ull d; asm("mov.b64 %0, {%1, %1};" : "=l"(d) : "f"(a)); return d;
}
__device__ __forceinline__ void unpack2(ull v, float& lo, float& hi) {
    asm("mov.b64 {%0, %1}, %2;" : "=f"(lo), "=f"(hi) : "l"(v));
}
__device__ __forceinline__ float lrelu(float v) { return fmaxf(v, 0.2f * v); }

// ---------------- smem layout (float offsets), all 16B aligned ----------------
#define XS   0            // x slice [j][r]: up to 32*256
#define W1T  8192         // W1 transposed [j=32][h=24]
#define B1   8960         // 24
#define W2T  8984         // W2 transposed [h=24][H=24]
#define B2   9560
#define W3T  9584
#define B3   10160
#define W4T  10184        // W4 transposed [h=24][o=2]  (s,t) pairs
#define B4   10232        // 2
#define SMF  10236

// 24->24 layer on a row-pair (unchanged from champion)
__device__ __forceinline__ void layer24(const float* __restrict__ a0,
                                        const float* __restrict__ a1,
                                        const float* wt, const float* bias,
                                        float* __restrict__ o0,
                                        float* __restrict__ o1)
{
    ull acc0[12], acc1[12];
    const ull* bp = (const ull*)bias;
    #pragma unroll
    for (int p = 0; p < 12; ++p) { acc0[p] = bp[p]; acc1[p] = bp[p]; }
    #pragma unroll
    for (int h = 0; h < 24; ++h) {
        const ull pa = dup2(a0[h]);
        const ull pb = dup2(a1[h]);
        const ulonglong2* w = (const ulonglong2*)(wt + h * 24);
        #pragma unroll
        for (int q = 0; q < 6; ++q) {
            const ulonglong2 wq = w[q];
            acc0[2*q]   = ffma2(wq.x, pa, acc0[2*q]);
            acc1[2*q]   = ffma2(wq.x, pb, acc1[2*q]);
            acc0[2*q+1] = ffma2(wq.y, pa, acc0[2*q+1]);
            acc1[2*q+1] = ffma2(wq.y, pb, acc1[2*q+1]);
        }
    }
    #pragma unroll
    for (int p = 0; p < 12; ++p) {
        float lo, hi;
        unpack2(acc0[p], lo, hi); o0[2*p] = lrelu(lo); o0[2*p+1] = lrelu(hi);
        unpack2(acc1[p], lo, hi); o1[2*p] = lrelu(lo); o1[2*p+1] = lrelu(hi);
    }
}

// ---------------- kernel 1: transpose x + dim-0 leaf + log_det init ----------------
__global__ void pack_x_kernel(const float* __restrict__ x,
                              const float* __restrict__ p0,
                              float* __restrict__ out)
{
    __shared__ float tile[128 * 33];
    const int tid  = threadIdx.x;
    const int base = blockIdx.x * 128;

    #pragma unroll
    for (int i = 0; i < 4; ++i) {
        const int idx = tid + i * 256;
        const int r  = idx >> 3;
        const int jc = idx & 7;
        const float4 v = ((const float4*)x)[(size_t)(base + r) * 8 + jc];
        tile[r * 33 + 4*jc + 0] = v.x;
        tile[r * 33 + 4*jc + 1] = v.y;
        tile[r * 33 + 4*jc + 2] = v.z;
        tile[r * 33 + 4*jc + 3] = v.w;
    }
    __syncthreads();

    #pragma unroll
    for (int i = 0; i < 16; ++i) {
        const int idx = tid + i * 256;
        const int j = idx >> 7;
        const int r = idx & 127;
        g_xt[j * BT + base + r] = tile[r * 33 + j];
    }

    if (tid < 128) {
        const float s0 = p0[0];
        // z col 31 = x[:,0]*exp(s0)+t0  (dim-0 LeafParam)
        out[(size_t)(base + tid) * 32 + 31] = tile[tid * 33] * expf(s0) + p0[1];
        // init log_det accumulator with s0; maf_main REDG-adds the 31 per-k s values
        out[(size_t)BT * 32 + base + tid] = s0;
    }
}

// ---------------- kernel 2: main — one (k, row-tile) per block ----------------
__global__ __launch_bounds__(BLK, 4)
void maf_main(const float* __restrict__ W1, const float* __restrict__ b1,
              const float* __restrict__ W2, const float* __restrict__ b2,
              const float* __restrict__ W3, const float* __restrict__ b3,
              const float* __restrict__ W4, const float* __restrict__ b4,
              float* __restrict__ out)
{
    __shared__ __align__(16) float sm[SMF];

    const int tid  = threadIdx.x;
    const int k    = blockIdx.y;
    const int base = blockIdx.x * 256;

    // ---- stage x slice (cols 0..k+1, float4) and transposed weights ----
    {
        const int nx4 = (k + 2) * 64;          // float4 count
        const float4* gx = (const float4*)g_xt;
        const int b4i = base >> 2;
        for (int idx = tid; idx < nx4; idx += BLK) {
            const int j  = idx >> 6;
            const int r4 = idx & 63;
            ((float4*)(sm + XS))[idx] = gx[j * (BT / 4) + b4i + r4];
        }

        const float* gW1 = W1 + k * 768;
        for (int i = tid; i < 768; i += BLK) {
            const int h = i >> 5, j = i & 31;
            sm[W1T + j * 24 + h] = gW1[i];
        }
        const float* gW2 = W2 + k * 576;
        for (int i = tid; i < 576; i += BLK)
            sm[W2T + (i % 24) * 24 + (i / 24)] = gW2[i];
        const float* gW3 = W3 + k * 576;
        for (int i = tid; i < 576; i += BLK)
            sm[W3T + (i % 24) * 24 + (i / 24)] = gW3[i];
        const float* gW4 = W4 + k * 48;
        for (int i = tid; i < 48; i += BLK)
            sm[W4T + (i % 24) * 2 + (i / 24)] = gW4[i];
        if (tid < 24) {
            sm[B1 + tid] = b1[k * 24 + tid];
            sm[B2 + tid] = b2[k * 24 + tid];
            sm[B3 + tid] = b3[k * 24 + tid];
        }
        if (tid < 2) sm[B4 + tid] = b4[k * 2 + tid];
    }
    __syncthreads();

    // this thread's two rows: base+tid and base+tid+128
    float a0[24], a1[24], c0[24], c1[24];

    // ---- layer 1: (k+1) -> 24, inputs from smem x slice ----
    {
        ull acc0[12], acc1[12];
        const ull* bp = (const ull*)(sm + B1);
        #pragma unroll
        for (int p = 0; p < 12; ++p) { acc0[p] = bp[p]; acc1[p] = bp[p]; }
        for (int j = 0; j <= k; ++j) {
            const ull pa = dup2(sm[XS + j * 256 + tid]);
            const ull pb = dup2(sm[XS + j * 256 + tid + 128]);
            const ulonglong2* w = (const ulonglong2*)(sm + W1T + j * 24);
            #pragma unroll
            for (int q = 0; q < 6; ++q) {
                const ulonglong2 wq = w[q];
                acc0[2*q]   = ffma2(wq.x, pa, acc0[2*q]);
                acc1[2*q]   = ffma2(wq.x, pb, acc1[2*q]);
                acc0[2*q+1] = ffma2(wq.y, pa, acc0[2*q+1]);
                acc1[2*q+1] = ffma2(wq.y, pb, acc1[2*q+1]);
            }
        }
        #pragma unroll
        for (int p = 0; p < 12; ++p) {
            float lo, hi;
            unpack2(acc0[p], lo, hi); a0[2*p] = lrelu(lo); a0[2*p+1] = lrelu(hi);
            unpack2(acc1[p], lo, hi); a1[2*p] = lrelu(lo); a1[2*p+1] = lrelu(hi);
        }
    }

    // ---- layers 2 & 3 ----
    layer24(a0, a1, sm + W2T, sm + B2, c0, c1);
    layer24(c0, c1, sm + W3T, sm + B3, a0, a1);

    // ---- layer 4: 24 -> (s, t), natural (s,t) pairs ----
    ull st0 = *(const ull*)(sm + B4);
    ull st1 = st0;
    #pragma unroll
    for (int h = 0; h < 24; ++h) {
        const ull w  = ((const ull*)(sm + W4T))[h];
        st0 = ffma2(w, dup2(a0[h]), st0);
        st1 = ffma2(w, dup2(a1[h]), st1);
    }
    float s0, t0, s1, t1;
    unpack2(st0, s0, t0);
    unpack2(st1, s1, t1);

    // ---- outputs: z[:, 30-k] = x[:, k+1]*exp(s)+t ; s -> log_det via REDG ----
    const int r0 = base + tid;
    const int r1 = base + tid + 128;
    const float xk0 = sm[XS + (k + 1) * 256 + tid];
    const float xk1 = sm[XS + (k + 1) * 256 + tid + 128];
    out[(size_t)r0 * 32 + (30 - k)] = xk0 * expf(s0) + t0;
    out[(size_t)r1 * 32 + (30 - k)] = xk1 * expf(s1) + t1;
    atomicAdd(out + (size_t)BT * 32 + r0, s0);
    atomicAdd(out + (size_t)BT * 32 + r1, s1);
}

extern "C" void kernel_launch(void* const* d_in, const int* in_sizes, int n_in,
                              void* d_out, int out_size)
{
    const float* x  = (const float*)d_in[0];
    const float* p0 = (const float*)d_in[1];
    const float* W1 = (const float*)d_in[2];
    const float* b1 = (const float*)d_in[3];
    const float* W2 = (const float*)d_in[4];
    const float* b2 = (const float*)d_in[5];
    const float* W3 = (const float*)d_in[6];
    const float* b3 = (const float*)d_in[7];
    const float* W4 = (const float*)d_in[8];
    const float* b4 = (const float*)d_in[9];
    float* out = (float*)d_out;

    pack_x_kernel<<<BT / 128, 256>>>(x, p0, out);
    maf_main<<<dim3(BT / 256, KM), BLK>>>(W1, b1, W2, b2, W3, b3, W4, b4, out);
}